// round 15
// baseline (speedup 1.0000x reference)
#include <cuda_runtime.h>
#include <cstdint>

// Shapes (fixed): predicted/target [32,4,512,512] f32; tokens unused;
// text_positions [32,64,2] f32. Output: 1 f32 scalar.
//
// result = [ sum(d^2) + 3 * sum_{masked px} d^2 ] / N,  d = p - t
//
// R9: TMA (cp.async.bulk) 3-stage SMEM pipeline for the 268MB stream.
// In-flight bytes now bounded by SMEM stages (8 CTA/SM x 3 x 8KB = 192KB/SM),
// not by the register file — the cap that pinned all LDG variants at <=74%
// DRAM. Paint/fixup/fold logic carried verbatim from R8 (proven correct).

#define NB 32
#define NC 4
#define NH 512
#define NW 512
#define NT 64
#define BOX 5

#define WORDS_PER_ROW   16
#define WORDS_PER_BATCH 8192
#define MASK_WORDS      262144        // 1 MB bitfield
#define N_ELEMS         33554432
#define N4              8388608       // float4 pairs

#define GRID     1184                 // 148 SMs * 8 CTAs: one full wave
#define THREADS  256
#define PAINT_CTAS 64

#define STAGES   3
#define CHUNK_F4 256                  // float4 per array per chunk (= THREADS)
#define CHUNK_BYTES 4096
#define NCHUNK   (N4 / CHUNK_F4)      // 32768

__device__ unsigned g_mask[MASK_WORDS];
__device__ float    g_partials[GRID];
__device__ unsigned g_count = 0;                 // wraps via atomicInc
__device__ volatile unsigned g_paint_done = 0;   // reset by last block

struct __align__(16) Smem {
    float4 pbuf[STAGES][CHUNK_F4];    // 12 KB
    float4 qbuf[STAGES][CHUNK_F4];    // 12 KB
    unsigned long long full[STAGES];
    unsigned long long empty[STAGES];
    float  ssum[THREADS / 32];
    double dsum[THREADS / 32];
    float  sx[NT], sy[NT];
    int    s_last;
};

__device__ __forceinline__ unsigned smem_u32(const void* p) {
    return (unsigned)__cvta_generic_to_shared(p);
}
__device__ __forceinline__ void mbar_init(unsigned a, unsigned cnt) {
    asm volatile("mbarrier.init.shared.b64 [%0], %1;" :: "r"(a), "r"(cnt) : "memory");
}
__device__ __forceinline__ void mbar_expect_tx(unsigned a, unsigned bytes) {
    asm volatile("mbarrier.arrive.expect_tx.shared.b64 _, [%0], %1;"
                 :: "r"(a), "r"(bytes) : "memory");
}
__device__ __forceinline__ void mbar_arrive(unsigned a) {
    asm volatile("mbarrier.arrive.shared.b64 _, [%0];" :: "r"(a) : "memory");
}
__device__ __forceinline__ void mbar_wait(unsigned a, unsigned parity) {
    asm volatile(
        "{\n\t.reg .pred P1;\n\t"
        "WL_%=:\n\t"
        "mbarrier.try_wait.parity.acquire.cta.shared::cta.b64 P1, [%0], %1, 0x989680;\n\t"
        "@P1 bra.uni WD_%=;\n\t"
        "bra.uni WL_%=;\n\t"
        "WD_%=:\n\t}"
        :: "r"(a), "r"(parity) : "memory");
}
__device__ __forceinline__ void bulk_g2s(unsigned dst, const void* src, unsigned bytes,
                                         unsigned mbar) {
    asm volatile(
        "cp.async.bulk.shared::cluster.global.mbarrier::complete_tx::bytes "
        "[%0], [%1], %2, [%3];"
        :: "r"(dst), "l"(src), "r"(bytes), "r"(mbar) : "memory");
}

__global__ void __launch_bounds__(THREADS, 8)
fused_loss_kernel(const float4* __restrict__ p4,
                  const float4* __restrict__ q4,
                  const float*  __restrict__ pf,
                  const float*  __restrict__ qf,
                  const float*  __restrict__ pos,
                  float* __restrict__ out) {
    __shared__ Smem sm;
    const int tid = threadIdx.x;
    const int bid = blockIdx.x;

    // ---- mbarrier init ----
    if (tid == 0) {
        #pragma unroll
        for (int s = 0; s < STAGES; s++) {
            mbar_init(smem_u32(&sm.full[s]),  1);        // expect_tx arrive
            mbar_init(smem_u32(&sm.empty[s]), THREADS);  // all consumers arrive
        }
    }
    __syncthreads();

    // ---- paint (CTAs 0..63, cold path; all CTAs co-resident) ----
    if (bid < PAINT_CTAS) {
        const int batch = bid >> 1;
        const int row   = ((bid & 1) << 8) + tid;
        if (tid < NT * 2) {
            float v = pos[(batch * NT) * 2 + tid];
            if (tid & 1) sm.sy[tid >> 1] = v; else sm.sx[tid >> 1] = v;
        }
        __syncthreads();
        unsigned w[WORDS_PER_ROW];
        #pragma unroll
        for (int k = 0; k < WORDS_PER_ROW; k++) w[k] = 0u;
        for (int t = 0; t < NT; t++) {
            float x = sm.sx[t], y = sm.sy[t];
            if (!(x > 0.0f && y > 0.0f)) continue;
            int yp = (int)floorf(y * (float)NH);
            if (row < yp - BOX || row >= yp + BOX) continue;
            int xp = (int)floorf(x * (float)NW);
            int x0 = max(xp - BOX, 0);
            int x1 = min(xp + BOX, NW);
            if (x0 >= x1) continue;
            int w0 = x0 >> 5, w1 = (x1 - 1) >> 5;
            if (w0 == w1) {
                w[w0] |= ((1u << (x1 - x0)) - 1u) << (x0 & 31);  // width<=10<32
            } else {
                w[w0] |= ~0u << (x0 & 31);
                w[w1] |= (1u << (x1 - (w1 << 5))) - 1u;          // 1..9 bits
            }
        }
        uint4* dst = (uint4*)&g_mask[batch * WORDS_PER_BATCH + row * WORDS_PER_ROW];
        #pragma unroll
        for (int k = 0; k < 4; k++)
            dst[k] = make_uint4(w[4*k], w[4*k+1], w[4*k+2], w[4*k+3]);
        __syncthreads();
        if (tid == 0) {
            __threadfence();
            atomicAdd((unsigned*)&g_paint_done, 1u);
        }
    }

    // ---- Phase A: TMA-pipelined stream of sum(d^2) ----
    const int nmine = (NCHUNK - bid + GRID - 1) / GRID;   // 27 or 28
    int ps = 0, pp = 1;   // producer cursor (phase=1: first empty-wait passes)
    int cs = 0, cp = 0;   // consumer cursor

    if (tid == 0) {
        const int npro = nmine < STAGES ? nmine : STAGES;
        for (int j = 0; j < npro; j++) {
            mbar_wait(smem_u32(&sm.empty[ps]), pp);
            mbar_expect_tx(smem_u32(&sm.full[ps]), 2 * CHUNK_BYTES);
            size_t c = (size_t)bid + (size_t)j * GRID;
            bulk_g2s(smem_u32(&sm.pbuf[ps][0]), p4 + c * CHUNK_F4, CHUNK_BYTES,
                     smem_u32(&sm.full[ps]));
            bulk_g2s(smem_u32(&sm.qbuf[ps][0]), q4 + c * CHUNK_F4, CHUNK_BYTES,
                     smem_u32(&sm.full[ps]));
            if (++ps == STAGES) { ps = 0; pp ^= 1; }
        }
    }

    float sum = 0.0f;
    for (int k = 0; k < nmine; k++) {
        mbar_wait(smem_u32(&sm.full[cs]), cp);
        float4 a = sm.pbuf[cs][tid];
        float4 b = sm.qbuf[cs][tid];
        float d0 = a.x - b.x, d1 = a.y - b.y, d2 = a.z - b.z, d3 = a.w - b.w;
        sum = fmaf(d0, d0, sum);
        sum = fmaf(d1, d1, sum);
        sum = fmaf(d2, d2, sum);
        sum = fmaf(d3, d3, sum);
        mbar_arrive(smem_u32(&sm.empty[cs]));
        if (++cs == STAGES) { cs = 0; cp ^= 1; }

        if (tid == 0 && k + STAGES < nmine) {
            mbar_wait(smem_u32(&sm.empty[ps]), pp);
            mbar_expect_tx(smem_u32(&sm.full[ps]), 2 * CHUNK_BYTES);
            size_t c = (size_t)bid + (size_t)(k + STAGES) * GRID;
            bulk_g2s(smem_u32(&sm.pbuf[ps][0]), p4 + c * CHUNK_F4, CHUNK_BYTES,
                     smem_u32(&sm.full[ps]));
            bulk_g2s(smem_u32(&sm.qbuf[ps][0]), q4 + c * CHUNK_F4, CHUNK_BYTES,
                     smem_u32(&sm.full[ps]));
            if (++ps == STAGES) { ps = 0; pp ^= 1; }
        }
    }

    // ---- wait for paint (stream >> paint; all CTAs resident) ----
    while (g_paint_done != PAINT_CTAS) { }
    __threadfence();

    // ---- Phase B: masked fixup, one mask word per thread ----
    {
        const int g = bid * THREADS + tid;
        if (g < MASK_WORDS) {
            unsigned w = g_mask[g];
            if (w) {
                const int batch = g >> 13;
                const int rem   = g & 8191;
                const int row   = rem >> 4;
                const int cbase = (rem & 15) << 5;
                const int base  = (batch << 20) + (row << 9);  // ch0 float idx
                float bsum = 0.0f;
                while (w) {
                    int bit = __ffs(w) - 1;
                    w &= w - 1;
                    int idx = base + cbase + bit;
                    #pragma unroll
                    for (int ch = 0; ch < NC; ch++) {
                        float d = pf[idx + (ch << 18)] - qf[idx + (ch << 18)];
                        bsum = fmaf(d, d, bsum);
                    }
                }
                sum = fmaf(3.0f, bsum, sum);
            }
        }
    }

    // ---- block reduce + last-block fold ----
    #pragma unroll
    for (int o = 16; o > 0; o >>= 1)
        sum += __shfl_xor_sync(0xFFFFFFFFu, sum, o);
    int lane = tid & 31, wid = tid >> 5;
    if (lane == 0) sm.ssum[wid] = sum;
    __syncthreads();
    if (wid == 0) {
        float v = (lane < THREADS / 32) ? sm.ssum[lane] : 0.0f;
        #pragma unroll
        for (int o = 4; o > 0; o >>= 1)
            v += __shfl_xor_sync(0xFFFFFFFFu, v, o);
        if (lane == 0) {
            g_partials[bid] = v;
            __threadfence();
            unsigned prev = atomicInc(&g_count, GRID - 1);
            sm.s_last = (prev == GRID - 1);
        }
    }
    __syncthreads();

    if (sm.s_last) {
        double d = 0.0;
        for (int i = tid; i < GRID; i += THREADS)
            d += (double)g_partials[i];
        #pragma unroll
        for (int o = 16; o > 0; o >>= 1)
            d += __shfl_xor_sync(0xFFFFFFFFu, d, o);
        if (lane == 0) sm.dsum[wid] = d;
        __syncthreads();
        if (wid == 0) {
            double t = (lane < THREADS / 32) ? sm.dsum[lane] : 0.0;
            #pragma unroll
            for (int o = 4; o > 0; o >>= 1)
                t += __shfl_xor_sync(0xFFFFFFFFu, t, o);
            if (lane == 0) {
                out[0] = (float)(t * (1.0 / (double)N_ELEMS));
                g_paint_done = 0;            // reset for next graph replay
                __threadfence();
            }
        }
    }
}

extern "C" void kernel_launch(void* const* d_in, const int* in_sizes, int n_in,
                              void* d_out, int out_size) {
    const float* pred = (const float*)d_in[0];
    const float* targ = (const float*)d_in[1];
    // d_in[2] (text_tokens) unused by the math.
    const float* pos  = (const float*)d_in[3];
    fused_loss_kernel<<<GRID, THREADS>>>((const float4*)pred,
                                         (const float4*)targ,
                                         pred, targ, pos, (float*)d_out);
}